// round 6
// baseline (speedup 1.0000x reference)
#include <cuda_runtime.h>
#include <math.h>

#define B_  2
#define S_  2048
#define D_  1024
#define H_  16
#define HD_ 64
#define M_  (B_ * S_)   // 4096

// ---------------- scratch (device globals; no runtime allocation) ----------
__device__ float g_q[(size_t)B_ * H_ * S_ * HD_];     // [B,H,S,hd]
__device__ float g_k[(size_t)B_ * H_ * S_ * HD_];
__device__ float g_v[(size_t)B_ * H_ * S_ * HD_];
__device__ float g_attn[(size_t)M_ * D_];             // [B,S,H,hd] == [B,S,D]

// ---------------------------------------------------------------------------
// 128x128x16 SGEMM, 256 threads, 8x8 register tile per thread.
// MODE 0: A = x param, W/bias chosen by blockIdx.z in {wq,wk,wv},
//         output permuted into g_q/g_k/g_v as [B,H,S,hd].
// MODE 1: A = g_attn global, W0/bias0 = wo/bo, output linear to Cout.
// ---------------------------------------------------------------------------
template <int MODE>
__global__ void __launch_bounds__(256)
gemm_kernel(const float* __restrict__ A,
            const float* __restrict__ W0, const float* __restrict__ bias0,
            const float* __restrict__ W1, const float* __restrict__ bias1,
            const float* __restrict__ W2, const float* __restrict__ bias2,
            float* __restrict__ Cout)
{
    __shared__ float As[16][132];   // [k][m], padded
    __shared__ float Bs[16][128];   // [k][n]

    const float* W    = W0;
    const float* bias = bias0;
    float*       dstq = nullptr;
    if (MODE == 0) {
        if (blockIdx.z == 0)      { W = W0; bias = bias0; dstq = g_q; }
        else if (blockIdx.z == 1) { W = W1; bias = bias1; dstq = g_k; }
        else                      { W = W2; bias = bias2; dstq = g_v; }
    }

    const float* Abase = (MODE == 0) ? A : (const float*)g_attn;

    const int tid  = threadIdx.x;
    const int tx   = tid & 15;          // 0..15 (n)
    const int ty   = tid >> 4;          // 0..15 (m)
    const int arow = tid >> 2;          // 0..63
    const int acol = (tid & 3) << 2;    // 0,4,8,12
    const int brow = tid >> 5;          // 0..7
    const int bcol = (tid & 31) << 2;   // 0..124

    const float* Ap = Abase + (size_t)blockIdx.y * 128 * D_;
    const float* Wp = W + blockIdx.x * 128;

    float acc[8][8];
#pragma unroll
    for (int i = 0; i < 8; i++)
#pragma unroll
        for (int j = 0; j < 8; j++) acc[i][j] = 0.f;

    for (int k0 = 0; k0 < D_; k0 += 16) {
        float4 a0 = *(const float4*)(Ap + (size_t)arow        * D_ + k0 + acol);
        float4 a1 = *(const float4*)(Ap + (size_t)(arow + 64) * D_ + k0 + acol);
        float4 b0 = *(const float4*)(Wp + (size_t)(k0 + brow)     * D_ + bcol);
        float4 b1 = *(const float4*)(Wp + (size_t)(k0 + brow + 8) * D_ + bcol);

        As[acol + 0][arow] = a0.x; As[acol + 1][arow] = a0.y;
        As[acol + 2][arow] = a0.z; As[acol + 3][arow] = a0.w;
        As[acol + 0][arow + 64] = a1.x; As[acol + 1][arow + 64] = a1.y;
        As[acol + 2][arow + 64] = a1.z; As[acol + 3][arow + 64] = a1.w;
        *(float4*)&Bs[brow][bcol]     = b0;
        *(float4*)&Bs[brow + 8][bcol] = b1;
        __syncthreads();

#pragma unroll
        for (int kk = 0; kk < 16; kk++) {
            float rm[8], rn[8];
            *(float4*)&rm[0] = *(const float4*)&As[kk][ty * 8];
            *(float4*)&rm[4] = *(const float4*)&As[kk][ty * 8 + 4];
            *(float4*)&rn[0] = *(const float4*)&Bs[kk][tx * 8];
            *(float4*)&rn[4] = *(const float4*)&Bs[kk][tx * 8 + 4];
#pragma unroll
            for (int i = 0; i < 8; i++)
#pragma unroll
                for (int j = 0; j < 8; j++)
                    acc[i][j] += rm[i] * rn[j];
        }
        __syncthreads();
    }

    // epilogue: add bias, store
#pragma unroll
    for (int i = 0; i < 8; i++) {
        const int m  = blockIdx.y * 128 + ty * 8 + i;
        const int bb = m / S_;
        const int ss = m % S_;
#pragma unroll
        for (int j = 0; j < 8; j++) {
            const int n = blockIdx.x * 128 + tx * 8 + j;
            const float v = acc[i][j] + bias[n];
            if (MODE == 0) {
                const int h = n >> 6;     // n / 64
                const int d = n & 63;
                dstq[((((size_t)bb * H_ + h) * S_ + ss) << 6) + d] = v;
            } else {
                Cout[(size_t)m * D_ + n] = v;
            }
        }
    }
}

// ---------------------------------------------------------------------------
// Flash attention (causal, fp32). One block = one (b,h) and 64 query rows.
// 256 threads = 64 rows x 4 column-groups. KV tiles of 32 rows.
// Thread (r,g): scores for columns c = g + 4*cc (cc 0..7),
//               output dims d = g*16 .. g*16+15 (contiguous, float4-stored).
// ---------------------------------------------------------------------------
__global__ void __launch_bounds__(256)
attn_kernel()
{
    __shared__ float Qs[64][68];   // padded: bank = 4r distinct per row
    __shared__ float Ks[32][68];   // padded: bank = 4c distinct per g
    __shared__ float Vs[32][64];
    __shared__ float Ps[64][36];   // bank = (4r+g) distinct across warp

    const int qt  = blockIdx.x;
    const int bh  = blockIdx.y;
    const int b   = bh >> 4;
    const int h   = bh & 15;
    const int tid = threadIdx.x;
    const int r   = tid >> 2;      // 0..63
    const int g   = tid & 3;       // 0..3
    const int q0  = qt * 64;
    const int qi  = q0 + r;

    const float* Qp = g_q + (size_t)bh * S_ * HD_;
    const float* Kp = g_k + (size_t)bh * S_ * HD_;
    const float* Vp = g_v + (size_t)bh * S_ * HD_;

    // load Q tile, pre-scaled by 1/sqrt(hd)
#pragma unroll
    for (int i = 0; i < 4; i++) {
        int idx = tid + i * 256;
        int row = idx >> 4;
        int col = (idx & 15) << 2;
        float4 qv = *(const float4*)(Qp + (size_t)(q0 + row) * HD_ + col);
        Qs[row][col + 0] = qv.x * 0.125f;
        Qs[row][col + 1] = qv.y * 0.125f;
        Qs[row][col + 2] = qv.z * 0.125f;
        Qs[row][col + 3] = qv.w * 0.125f;
    }

    float m_i = -1e30f, l_i = 0.f;
    float O[16];
#pragma unroll
    for (int d = 0; d < 16; d++) O[d] = 0.f;

    const int ntiles = (q0 + 64) / 32;   // causal: 2*(qt+1) KV tiles
    for (int t = 0; t < ntiles; t++) {
        const int k0 = t * 32;
        __syncthreads();   // previous tile's Ks/Vs reads done
#pragma unroll
        for (int i = 0; i < 2; i++) {
            int idx = tid + i * 256;
            int row = idx >> 4;
            int col = (idx & 15) << 2;
            float4 kv = *(const float4*)(Kp + (size_t)(k0 + row) * HD_ + col);
            Ks[row][col + 0] = kv.x; Ks[row][col + 1] = kv.y;
            Ks[row][col + 2] = kv.z; Ks[row][col + 3] = kv.w;
            float4 vv = *(const float4*)(Vp + (size_t)(k0 + row) * HD_ + col);
            *(float4*)&Vs[row][col] = vv;
        }
        __syncthreads();

        // scores: 8 columns per thread, dot over 64 dims (float4-vectorized)
        float sc[8];
#pragma unroll
        for (int cc = 0; cc < 8; cc++) sc[cc] = 0.f;
#pragma unroll
        for (int k4 = 0; k4 < 16; k4++) {
            float4 qv = *(const float4*)&Qs[r][k4 * 4];
#pragma unroll
            for (int cc = 0; cc < 8; cc++) {
                const int c = g + cc * 4;
                float4 kv = *(const float4*)&Ks[c][k4 * 4];
                sc[cc] += qv.x * kv.x + qv.y * kv.y + qv.z * kv.z + qv.w * kv.w;
            }
        }
        // causal mask
#pragma unroll
        for (int cc = 0; cc < 8; cc++) {
            const int kj = k0 + g + cc * 4;
            if (kj > qi) sc[cc] = -1e30f;
        }

        // online softmax (row = 4 consecutive lanes)
        float mx = sc[0];
#pragma unroll
        for (int cc = 1; cc < 8; cc++) mx = fmaxf(mx, sc[cc]);
        mx = fmaxf(mx, __shfl_xor_sync(0xffffffffu, mx, 1));
        mx = fmaxf(mx, __shfl_xor_sync(0xffffffffu, mx, 2));
        const float m_new = fmaxf(m_i, mx);
        const float alpha = __expf(m_i - m_new);

        float ls = 0.f;
#pragma unroll
        for (int cc = 0; cc < 8; cc++) {
            const float p = __expf(sc[cc] - m_new);
            Ps[r][g + cc * 4] = p;
            ls += p;
        }
        ls += __shfl_xor_sync(0xffffffffu, ls, 1);
        ls += __shfl_xor_sync(0xffffffffu, ls, 2);
        l_i = l_i * alpha + ls;
        m_i = m_new;
#pragma unroll
        for (int d = 0; d < 16; d++) O[d] *= alpha;
        __syncwarp();   // Ps row produced/consumed within one warp

        // O += P @ V  (thread owns dims g*16 .. g*16+15)
#pragma unroll
        for (int c = 0; c < 32; c++) {
            const float p = Ps[r][c];
            float4 v0 = *(const float4*)&Vs[c][g * 16 + 0];
            float4 v1 = *(const float4*)&Vs[c][g * 16 + 4];
            float4 v2 = *(const float4*)&Vs[c][g * 16 + 8];
            float4 v3 = *(const float4*)&Vs[c][g * 16 + 12];
            O[0]  += p * v0.x; O[1]  += p * v0.y; O[2]  += p * v0.z; O[3]  += p * v0.w;
            O[4]  += p * v1.x; O[5]  += p * v1.y; O[6]  += p * v1.z; O[7]  += p * v1.w;
            O[8]  += p * v2.x; O[9]  += p * v2.y; O[10] += p * v2.z; O[11] += p * v2.w;
            O[12] += p * v3.x; O[13] += p * v3.y; O[14] += p * v3.z; O[15] += p * v3.w;
        }
    }

    // finalize: divide by l, write to [B,S,H,hd] (== [B,S,D])
    const float inv = 1.f / l_i;
    float* Op = g_attn + (((size_t)b * S_ + qi) * H_ + h) * HD_ + g * 16;
#pragma unroll
    for (int q4 = 0; q4 < 4; q4++) {
        float4 o;
        o.x = O[q4 * 4 + 0] * inv;
        o.y = O[q4 * 4 + 1] * inv;
        o.z = O[q4 * 4 + 2] * inv;
        o.w = O[q4 * 4 + 3] * inv;
        *(float4*)(Op + q4 * 4) = o;
    }
}

// ---------------------------------------------------------------------------
extern "C" void kernel_launch(void* const* d_in, const int* in_sizes, int n_in,
                              void* d_out, int out_size)
{
    const float* x  = (const float*)d_in[0];
    const float* wq = (const float*)d_in[1];
    const float* bq = (const float*)d_in[2];
    const float* wk = (const float*)d_in[3];
    const float* bk = (const float*)d_in[4];
    const float* wv = (const float*)d_in[5];
    const float* bv = (const float*)d_in[6];
    const float* wo = (const float*)d_in[7];
    const float* bo = (const float*)d_in[8];
    float* out = (float*)d_out;

    // 1) fused QKV projections -> g_q/g_k/g_v in [B,H,S,hd]
    dim3 gq(D_ / 128, M_ / 128, 3);
    gemm_kernel<0><<<gq, 256>>>(x, wq, bq, wk, bk, wv, bv, nullptr);

    // 2) causal flash attention -> g_attn in [B,S,D]
    dim3 ga(S_ / 64, B_ * H_);
    attn_kernel<<<ga, 256>>>();

    // 3) output projection -> d_out
    dim3 go(D_ / 128, M_ / 128, 1);
    gemm_kernel<1><<<go, 256>>>(nullptr, wo, bo, nullptr, nullptr, nullptr, nullptr, out);
}

// round 7
// speedup vs baseline: 1.8738x; 1.8738x over previous
#include <cuda_runtime.h>
#include <math.h>

#define B_  2
#define S_  2048
#define D_  1024
#define H_  16
#define HD_ 64
#define M_  (B_ * S_)   // 4096

// ---------------- scratch (device globals; no runtime allocation) ----------
__device__ float g_q[(size_t)B_ * H_ * S_ * HD_];     // [B,H,S,hd]
__device__ float g_k[(size_t)B_ * H_ * S_ * HD_];
__device__ float g_v[(size_t)B_ * H_ * S_ * HD_];
__device__ float g_attn[(size_t)M_ * D_];             // [B,S,H,hd] == [B,S,D]

// ---------------------------------------------------------------------------
// 128x128x16 SGEMM, 256 threads, 8x8 register tile per thread. (unchanged)
// ---------------------------------------------------------------------------
template <int MODE>
__global__ void __launch_bounds__(256)
gemm_kernel(const float* __restrict__ A,
            const float* __restrict__ W0, const float* __restrict__ bias0,
            const float* __restrict__ W1, const float* __restrict__ bias1,
            const float* __restrict__ W2, const float* __restrict__ bias2,
            float* __restrict__ Cout)
{
    __shared__ float As[16][132];   // [k][m], padded
    __shared__ float Bs[16][128];   // [k][n]

    const float* W    = W0;
    const float* bias = bias0;
    float*       dstq = nullptr;
    if (MODE == 0) {
        if (blockIdx.z == 0)      { W = W0; bias = bias0; dstq = g_q; }
        else if (blockIdx.z == 1) { W = W1; bias = bias1; dstq = g_k; }
        else                      { W = W2; bias = bias2; dstq = g_v; }
    }

    const float* Abase = (MODE == 0) ? A : (const float*)g_attn;

    const int tid  = threadIdx.x;
    const int tx   = tid & 15;
    const int ty   = tid >> 4;
    const int arow = tid >> 2;
    const int acol = (tid & 3) << 2;
    const int brow = tid >> 5;
    const int bcol = (tid & 31) << 2;

    const float* Ap = Abase + (size_t)blockIdx.y * 128 * D_;
    const float* Wp = W + blockIdx.x * 128;

    float acc[8][8];
#pragma unroll
    for (int i = 0; i < 8; i++)
#pragma unroll
        for (int j = 0; j < 8; j++) acc[i][j] = 0.f;

    for (int k0 = 0; k0 < D_; k0 += 16) {
        float4 a0 = *(const float4*)(Ap + (size_t)arow        * D_ + k0 + acol);
        float4 a1 = *(const float4*)(Ap + (size_t)(arow + 64) * D_ + k0 + acol);
        float4 b0 = *(const float4*)(Wp + (size_t)(k0 + brow)     * D_ + bcol);
        float4 b1 = *(const float4*)(Wp + (size_t)(k0 + brow + 8) * D_ + bcol);

        As[acol + 0][arow] = a0.x; As[acol + 1][arow] = a0.y;
        As[acol + 2][arow] = a0.z; As[acol + 3][arow] = a0.w;
        As[acol + 0][arow + 64] = a1.x; As[acol + 1][arow + 64] = a1.y;
        As[acol + 2][arow + 64] = a1.z; As[acol + 3][arow + 64] = a1.w;
        *(float4*)&Bs[brow][bcol]     = b0;
        *(float4*)&Bs[brow + 8][bcol] = b1;
        __syncthreads();

#pragma unroll
        for (int kk = 0; kk < 16; kk++) {
            float rm[8], rn[8];
            *(float4*)&rm[0] = *(const float4*)&As[kk][ty * 8];
            *(float4*)&rm[4] = *(const float4*)&As[kk][ty * 8 + 4];
            *(float4*)&rn[0] = *(const float4*)&Bs[kk][tx * 8];
            *(float4*)&rn[4] = *(const float4*)&Bs[kk][tx * 8 + 4];
#pragma unroll
            for (int i = 0; i < 8; i++)
#pragma unroll
                for (int j = 0; j < 8; j++)
                    acc[i][j] += rm[i] * rn[j];
        }
        __syncthreads();
    }

#pragma unroll
    for (int i = 0; i < 8; i++) {
        const int m  = blockIdx.y * 128 + ty * 8 + i;
        const int bb = m / S_;
        const int ss = m % S_;
#pragma unroll
        for (int j = 0; j < 8; j++) {
            const int n = blockIdx.x * 128 + tx * 8 + j;
            const float v = acc[i][j] + bias[n];
            if (MODE == 0) {
                const int h = n >> 6;
                const int d = n & 63;
                dstq[((((size_t)bb * H_ + h) * S_ + ss) << 6) + d] = v;
            } else {
                Cout[(size_t)m * D_ + n] = v;
            }
        }
    }
}

// ---------------------------------------------------------------------------
// Flash attention v2 (causal, fp32): register-tiled micro-GEMMs.
// Block = 128 q rows x one (b,h). KV tile = 64. 256 threads as 16x16.
// Thread (ty,tx): 8 rows (ty*8..+7) x 4 cols/dims (tx*4..+3).
// smem (dynamic, 101 KB):
//   Qs[64][132]  k-major Q     (33792 B)
//   Ks[64][68]   k-major K     (17408 B)
//   Vs[64][68]   row-major V   (17408 B)
//   Ps[128][68]  row-major P   (34816 B)
// ---------------------------------------------------------------------------
#define QS_OFF 0
#define KS_OFF (64 * 132)
#define VS_OFF (KS_OFF + 64 * 68)
#define PS_OFF (VS_OFF + 64 * 68)
#define SMEM_FLOATS (PS_OFF + 128 * 68)

__global__ void __launch_bounds__(256)
attn_kernel()
{
    extern __shared__ float sm[];
    float (*Qs)[132] = (float(*)[132])(sm + QS_OFF);
    float (*Ks)[68]  = (float(*)[68])(sm + KS_OFF);
    float (*Vs)[68]  = (float(*)[68])(sm + VS_OFF);
    float (*Ps)[68]  = (float(*)[68])(sm + PS_OFF);

    const int qt  = blockIdx.x;
    const int bh  = blockIdx.y;
    const int b   = bh >> 4;
    const int h   = bh & 15;
    const int tid = threadIdx.x;
    const int tx  = tid & 15;
    const int ty  = tid >> 4;
    const int q0  = qt * 128;

    const float* Qp = g_q + (size_t)bh * S_ * HD_;
    const float* Kp = g_k + (size_t)bh * S_ * HD_;
    const float* Vp = g_v + (size_t)bh * S_ * HD_;

    // ---- load Q tile transposed (k-major), pre-scaled by 1/sqrt(hd) ----
#pragma unroll
    for (int i = 0; i < 8; i++) {
        const int e  = tid + i * 256;      // 0..2047
        const int r  = e & 127;            // lanes vary r -> conflict-free STS
        const int k4 = e >> 7;             // 0..15
        float4 qv = *(const float4*)(Qp + (size_t)(q0 + r) * HD_ + k4 * 4);
        Qs[k4 * 4 + 0][r] = qv.x * 0.125f;
        Qs[k4 * 4 + 1][r] = qv.y * 0.125f;
        Qs[k4 * 4 + 2][r] = qv.z * 0.125f;
        Qs[k4 * 4 + 3][r] = qv.w * 0.125f;
    }

    float m_i[8], l_i[8];
    float O[8][4];
#pragma unroll
    for (int i = 0; i < 8; i++) {
        m_i[i] = -1e30f; l_i[i] = 0.f;
#pragma unroll
        for (int j = 0; j < 4; j++) O[i][j] = 0.f;
    }

    const int ntiles = 2 * qt + 2;   // causal
    for (int t = 0; t < ntiles; t++) {
        const int k0 = t * 64;
        __syncthreads();   // prior-tile Ks/Vs/Ps reads complete

        // ---- load K (transposed to k-major) and V (row-major) ----
#pragma unroll
        for (int i = 0; i < 4; i++) {
            const int e  = tid + i * 256;  // 0..1023
            const int c  = e & 63;
            const int k4 = e >> 6;         // 0..15
            float4 kv = *(const float4*)(Kp + (size_t)(k0 + c) * HD_ + k4 * 4);
            Ks[k4 * 4 + 0][c] = kv.x;
            Ks[k4 * 4 + 1][c] = kv.y;
            Ks[k4 * 4 + 2][c] = kv.z;
            Ks[k4 * 4 + 3][c] = kv.w;
            const int vc = e >> 4;         // 0..63
            const int d4 = e & 15;
            float4 vv = *(const float4*)(Vp + (size_t)(k0 + vc) * HD_ + d4 * 4);
            *(float4*)&Vs[vc][d4 * 4] = vv;
        }
        __syncthreads();

        // ---- scores: 8x4 register tile over k = 0..63 ----
        float sc[8][4];
#pragma unroll
        for (int i = 0; i < 8; i++)
#pragma unroll
            for (int j = 0; j < 4; j++) sc[i][j] = 0.f;

#pragma unroll 8
        for (int k = 0; k < 64; k++) {
            float rm[8], rn[4];
            *(float4*)&rm[0] = *(const float4*)&Qs[k][ty * 8];
            *(float4*)&rm[4] = *(const float4*)&Qs[k][ty * 8 + 4];
            *(float4*)&rn[0] = *(const float4*)&Ks[k][tx * 4];
#pragma unroll
            for (int i = 0; i < 8; i++)
#pragma unroll
                for (int j = 0; j < 4; j++)
                    sc[i][j] += rm[i] * rn[j];
        }

        // ---- causal mask (only the last two tiles touch the diagonal) ----
        if (t + 2 >= ntiles) {
#pragma unroll
            for (int i = 0; i < 8; i++) {
                const int qi = q0 + ty * 8 + i;
#pragma unroll
                for (int j = 0; j < 4; j++)
                    if (k0 + tx * 4 + j > qi) sc[i][j] = -1e30f;
            }
        }

        // ---- online softmax: row reductions across the 16 tx lanes ----
        float mx[8];
#pragma unroll
        for (int i = 0; i < 8; i++) {
            float v = fmaxf(fmaxf(sc[i][0], sc[i][1]), fmaxf(sc[i][2], sc[i][3]));
            v = fmaxf(v, __shfl_xor_sync(0xffffffffu, v, 1));
            v = fmaxf(v, __shfl_xor_sync(0xffffffffu, v, 2));
            v = fmaxf(v, __shfl_xor_sync(0xffffffffu, v, 4));
            v = fmaxf(v, __shfl_xor_sync(0xffffffffu, v, 8));
            mx[i] = v;
        }
#pragma unroll
        for (int i = 0; i < 8; i++) {
            const float m_new = fmaxf(m_i[i], mx[i]);
            const float alpha = __expf(m_i[i] - m_new);
            float p0 = __expf(sc[i][0] - m_new);
            float p1 = __expf(sc[i][1] - m_new);
            float p2 = __expf(sc[i][2] - m_new);
            float p3 = __expf(sc[i][3] - m_new);
            *(float4*)&Ps[ty * 8 + i][tx * 4] = make_float4(p0, p1, p2, p3);
            float ls = (p0 + p1) + (p2 + p3);
            ls += __shfl_xor_sync(0xffffffffu, ls, 1);
            ls += __shfl_xor_sync(0xffffffffu, ls, 2);
            ls += __shfl_xor_sync(0xffffffffu, ls, 4);
            ls += __shfl_xor_sync(0xffffffffu, ls, 8);
            l_i[i] = l_i[i] * alpha + ls;
            m_i[i] = m_new;
            O[i][0] *= alpha; O[i][1] *= alpha;
            O[i][2] *= alpha; O[i][3] *= alpha;
        }
        __syncthreads();   // Ps complete before cross-warp PV reads

        // ---- O += P @ V : 8x4 register tile, 4 kv columns per step ----
#pragma unroll 1
        for (int c4 = 0; c4 < 16; c4++) {
            const int c = c4 * 4;
            float v0[4], v1[4], v2[4], v3[4];
            *(float4*)&v0[0] = *(const float4*)&Vs[c + 0][tx * 4];
            *(float4*)&v1[0] = *(const float4*)&Vs[c + 1][tx * 4];
            *(float4*)&v2[0] = *(const float4*)&Vs[c + 2][tx * 4];
            *(float4*)&v3[0] = *(const float4*)&Vs[c + 3][tx * 4];
#pragma unroll
            for (int i = 0; i < 8; i++) {
                float4 pm = *(const float4*)&Ps[ty * 8 + i][c];
#pragma unroll
                for (int j = 0; j < 4; j++)
                    O[i][j] += pm.x * v0[j] + pm.y * v1[j] + pm.z * v2[j] + pm.w * v3[j];
            }
        }
    }

    // ---- finalize: divide by l, write to [B,S,H,hd] (== [B,S,D]) ----
#pragma unroll
    for (int i = 0; i < 8; i++) {
        const float inv = 1.f / l_i[i];
        const int qi = q0 + ty * 8 + i;
        float4 o;
        o.x = O[i][0] * inv; o.y = O[i][1] * inv;
        o.z = O[i][2] * inv; o.w = O[i][3] * inv;
        *(float4*)(g_attn + ((size_t)(b * S_ + qi)) * D_ + h * HD_ + tx * 4) = o;
    }
}

// ---------------------------------------------------------------------------
extern "C" void kernel_launch(void* const* d_in, const int* in_sizes, int n_in,
                              void* d_out, int out_size)
{
    const float* x  = (const float*)d_in[0];
    const float* wq = (const float*)d_in[1];
    const float* bq = (const float*)d_in[2];
    const float* wk = (const float*)d_in[3];
    const float* bk = (const float*)d_in[4];
    const float* wv = (const float*)d_in[5];
    const float* bv = (const float*)d_in[6];
    const float* wo = (const float*)d_in[7];
    const float* bo = (const float*)d_in[8];
    float* out = (float*)d_out;

    static int smem_set = 0;
    if (!smem_set) {
        cudaFuncSetAttribute(attn_kernel,
                             cudaFuncAttributeMaxDynamicSharedMemorySize,
                             SMEM_FLOATS * (int)sizeof(float));
        smem_set = 1;
    }

    // 1) fused QKV projections -> g_q/g_k/g_v in [B,H,S,hd]
    dim3 gq(D_ / 128, M_ / 128, 3);
    gemm_kernel<0><<<gq, 256>>>(x, wq, bq, wk, bk, wv, bv, nullptr);

    // 2) causal flash attention -> g_attn in [B,S,D]
    dim3 ga(S_ / 128, B_ * H_);
    attn_kernel<<<ga, 256, SMEM_FLOATS * (int)sizeof(float)>>>();

    // 3) output projection -> d_out
    dim3 go(D_ / 128, M_ / 128, 1);
    gemm_kernel<1><<<go, 256>>>(nullptr, wo, bo, nullptr, nullptr, nullptr, nullptr, out);
}